// round 1
// baseline (speedup 1.0000x reference)
#include <cuda_runtime.h>
#include <math.h>

#define G  4384
#define D  128
#define B  8
#define F  4
#define H1 64
#define NOUT 26
#define NQC 16          // q-chunks in K2 (4384/16 = 274 exactly)
#define KP  8           // k columns per thread in K2

// ---------------- device scratch (no allocations allowed) ----------------
__device__ float4 g_P4[G];            // P'[k] = (W_in @ K^T) * scale * log2e, packed per k
__device__ float  g_c[G];             // c'[k] = (b_in @ K^T) * scale * log2e
__device__ float  g_R[B * G];         // 1/Z per (b,q)
__device__ float  g_acc[B * G + B * D]; // [0, B*G): w column sums; [B*G, ...): mean partials

// ---------------- K0: P[4,G] and c[G] ----------------
__global__ void k0_P(const float* __restrict__ Win, const float* __restrict__ bin,
                     const float* __restrict__ Kp) {
    int warp = (blockIdx.x * blockDim.x + threadIdx.x) >> 5;
    int lane = threadIdx.x & 31;
    if (warp >= G) return;
    // scale * log2(e) = (1/sqrt(128)) * 1.4426950408889634
    const float S = 1.4426950408889634f * 0.08838834764831843f;
    float a0 = 0.f, a1 = 0.f, a2 = 0.f, a3 = 0.f, cb = 0.f;
    const float* krow = Kp + (size_t)warp * D;
#pragma unroll
    for (int i = 0; i < 4; i++) {
        int d = lane + 32 * i;
        float kv = krow[d];
        a0 = fmaf(kv, Win[0 * D + d], a0);
        a1 = fmaf(kv, Win[1 * D + d], a1);
        a2 = fmaf(kv, Win[2 * D + d], a2);
        a3 = fmaf(kv, Win[3 * D + d], a3);
        cb = fmaf(kv, bin[d], cb);
    }
#pragma unroll
    for (int off = 16; off; off >>= 1) {
        a0 += __shfl_down_sync(0xffffffffu, a0, off);
        a1 += __shfl_down_sync(0xffffffffu, a1, off);
        a2 += __shfl_down_sync(0xffffffffu, a2, off);
        a3 += __shfl_down_sync(0xffffffffu, a3, off);
        cb += __shfl_down_sync(0xffffffffu, cb, off);
    }
    if (lane == 0) {
        g_P4[warp] = make_float4(a0 * S, a1 * S, a2 * S, a3 * S);
        g_c[warp]  = cb * S;
    }
}

// ---------------- K1: row sums Z -> write 1/Z ----------------
// grid (137, 8), block 256. Block owns (b, 32 queries) over all k.
// 4 groups of 64 threads; each group handles 8 queries; each thread holds the
// group's 8 query m-vectors in regs, strides k by 64.
extern __shared__ float k1_smem[];
__global__ void __launch_bounds__(256) k1_Z(const float* __restrict__ mut) {
    float4* sP = (float4*)k1_smem;
    float*  sC = k1_smem + G * 4;
    int tid = threadIdx.x;
    for (int i = tid; i < G; i += 256) { sP[i] = g_P4[i]; sC[i] = g_c[i]; }
    __syncthreads();

    int b = blockIdx.y;
    int qbase = blockIdx.x * 32;
    int group = tid >> 6;     // 0..3
    int klane = tid & 63;

    float4 m[8];
    const float4* mp = (const float4*)mut + (size_t)b * G + qbase + group * 8;
#pragma unroll
    for (int j = 0; j < 8; j++) m[j] = mp[j];

    float z[8];
#pragma unroll
    for (int j = 0; j < 8; j++) z[j] = 0.f;

    for (int k = klane; k < G; k += 64) {
        float4 p = sP[k];
        float  c = sC[k];
#pragma unroll
        for (int j = 0; j < 8; j++) {
            float s = fmaf(m[j].x, p.x, fmaf(m[j].y, p.y, fmaf(m[j].z, p.z, fmaf(m[j].w, p.w, c))));
            float e;
            asm("ex2.approx.f32 %0, %1;" : "=f"(e) : "f"(s));
            z[j] += e;
        }
    }
    // reduce over 32 lanes (each warp covers a disjoint k subset, same 8 queries)
#pragma unroll
    for (int j = 0; j < 8; j++) {
#pragma unroll
        for (int off = 16; off; off >>= 1)
            z[j] += __shfl_down_sync(0xffffffffu, z[j], off);
    }
    __syncthreads();   // all done reading sP before reuse
    int warp = tid >> 5, lane = tid & 31;
    if (lane == 0) {
#pragma unroll
        for (int j = 0; j < 8; j++) k1_smem[warp * 8 + j] = z[j];
    }
    __syncthreads();
    if (tid < 32) {
        int g = tid >> 3, j = tid & 7;        // query = g*8 + j; its warps are 2g, 2g+1
        float Z = k1_smem[(2 * g) * 8 + j] + k1_smem[(2 * g + 1) * 8 + j];
        g_R[b * G + qbase + g * 8 + j] = 1.0f / Z;
    }
}

// ---------------- K2: column sums w[b,k] = sum_q exp(s)/Z_q ----------------
// grid (NQC, 3, 8), block 256. P tile lives in registers (KP cols per thread).
__global__ void __launch_bounds__(256) k2_W(const float* __restrict__ mut) {
    int b     = blockIdx.z;
    int ktile = blockIdx.y;      // 0..2, tiles of 2048
    int qc    = blockIdx.x;      // 0..NQC-1
    int tid   = threadIdx.x;
    int k0    = ktile * 2048;

    float4 p[KP]; float c[KP]; float w[KP]; int kk[KP];
#pragma unroll
    for (int j = 0; j < KP; j++) {
        int k = k0 + j * 256 + tid;
        kk[j] = k;
        if (k < G) { p[j] = g_P4[k]; c[j] = g_c[k]; }
        else       { p[j] = make_float4(0.f, 0.f, 0.f, 0.f); c[j] = -10000.f; }
        w[j] = 0.f;
    }

    __shared__ float4 sm[128];
    __shared__ float  sr[128];
    int qstart = qc * (G / NQC);
    int qend   = qstart + (G / NQC);

    for (int q0 = qstart; q0 < qend; q0 += 128) {
        int nq = qend - q0; if (nq > 128) nq = 128;
        __syncthreads();
        if (tid < nq) {
            sm[tid] = ((const float4*)mut)[(size_t)b * G + q0 + tid];
            sr[tid] = g_R[b * G + q0 + tid];
        }
        __syncthreads();
        for (int qq = 0; qq < nq; qq++) {
            float4 m = sm[qq];
            float  r = sr[qq];
#pragma unroll
            for (int j = 0; j < KP; j++) {
                float s = fmaf(m.x, p[j].x, fmaf(m.y, p[j].y, fmaf(m.z, p[j].z, fmaf(m.w, p[j].w, c[j]))));
                float e;
                asm("ex2.approx.f32 %0, %1;" : "=f"(e) : "f"(s));
                w[j] = fmaf(e, r, w[j]);
            }
        }
    }
#pragma unroll
    for (int j = 0; j < KP; j++)
        if (kk[j] < G) atomicAdd(&g_acc[b * G + kk[j]], w[j]);
}

// ---------------- K3a: mean partials = (w @ V) ----------------
__global__ void k3a(const float* __restrict__ V) {
    int b = blockIdx.x, chunk = blockIdx.y, d = threadIdx.x;
    int kstart = chunk * (G / 16), kend = kstart + (G / 16);
    float acc = 0.f;
    for (int k = kstart; k < kend; k++)
        acc = fmaf(g_acc[b * G + k], V[(size_t)k * D + d], acc);
    atomicAdd(&g_acc[B * G + b * D + d], acc);
}

// ---------------- K3b: GELU MLP head ----------------
__global__ void k3b(const float* __restrict__ W1, const float* __restrict__ b1,
                    const float* __restrict__ W2, const float* __restrict__ b2,
                    float* __restrict__ out) {
    __shared__ float mean[D];
    __shared__ float h[H1];
    int b = blockIdx.x, tid = threadIdx.x;
    mean[tid] = g_acc[B * G + b * D + tid] * (1.0f / (float)G);
    __syncthreads();
    if (tid < H1) {
        float a = b1[tid];
        for (int d = 0; d < D; d++) a = fmaf(mean[d], W1[d * H1 + tid], a);
        h[tid] = 0.5f * a * (1.0f + erff(a * 0.70710678118654752f));
    }
    __syncthreads();
    if (tid < NOUT) {
        float o = b2[tid];
        for (int j = 0; j < H1; j++) o = fmaf(h[j], W2[j * NOUT + tid], o);
        out[b * NOUT + tid] = o;
    }
}

// ---------------- launch ----------------
extern "C" void kernel_launch(void* const* d_in, const int* in_sizes, int n_in,
                              void* d_out, int out_size) {
    const float* mut = (const float*)d_in[0];   // [8,4384,4]
    const float* V   = (const float*)d_in[1];   // [4384,128]
    const float* Win = (const float*)d_in[2];   // [4,128]
    const float* bin = (const float*)d_in[3];   // [128]
    const float* Kp  = (const float*)d_in[4];   // [4384,128]
    const float* W1  = (const float*)d_in[5];   // [128,64]
    const float* b1  = (const float*)d_in[6];   // [64]
    const float* W2  = (const float*)d_in[7];   // [64,26]
    const float* b2  = (const float*)d_in[8];   // [26]
    float* out = (float*)d_out;                 // [8,26]
    (void)in_sizes; (void)n_in; (void)out_size;

    void* accPtr = nullptr;
    cudaGetSymbolAddress(&accPtr, g_acc);
    cudaMemsetAsync(accPtr, 0, sizeof(float) * (B * G + B * D), 0);

    k0_P<<<548, 256>>>(Win, bin, Kp);   // 548*8 warps = 4384 = G

    size_t smemK1 = (size_t)G * 16 + (size_t)G * 4;   // 87680 B
    cudaFuncSetAttribute(k1_Z, cudaFuncAttributeMaxDynamicSharedMemorySize, (int)smemK1);
    k1_Z<<<dim3(G / 32, B), 256, smemK1>>>(mut);

    k2_W<<<dim3(NQC, 3, B), 256>>>(mut);

    k3a<<<dim3(B, 16), D>>>(V);
    k3b<<<B, D>>>(W1, b1, W2, b2, out);
}

// round 3
// speedup vs baseline: 1.0888x; 1.0888x over previous
#include <cuda_runtime.h>
#include <math.h>

#define G  4384
#define D  128
#define B  8
#define H1 64
#define NOUT 26
#define QB 8                  // queries per block in fused kernel (G/QB = 548 exact)
#define NT 512                // threads per block in fused kernel

// ---------------- device scratch ----------------
__device__ float4 g_P4[G];              // P'[k] = (W_in @ K^T)*scale*log2e
__device__ float  g_c[G];               // c'[k]
__device__ float  g_acc[B * G + B * D]; // [0,B*G): w column sums; then mean partials

__device__ __forceinline__ float ex2f(float x) {
    float e; asm("ex2.approx.f32 %0, %1;" : "=f"(e) : "f"(x)); return e;
}

// ---------------- K0: P[4,G] and c[G] ----------------
__global__ void k0_P(const float* __restrict__ Win, const float* __restrict__ bin,
                     const float* __restrict__ Kp) {
    int warp = (blockIdx.x * blockDim.x + threadIdx.x) >> 5;
    int lane = threadIdx.x & 31;
    if (warp >= G) return;
    const float S = 1.4426950408889634f * 0.08838834764831843f;  // log2e / sqrt(128)
    float a0 = 0.f, a1 = 0.f, a2 = 0.f, a3 = 0.f, cb = 0.f;
    const float* krow = Kp + (size_t)warp * D;
#pragma unroll
    for (int i = 0; i < 4; i++) {
        int d = lane + 32 * i;
        float kv = krow[d];
        a0 = fmaf(kv, Win[0 * D + d], a0);
        a1 = fmaf(kv, Win[1 * D + d], a1);
        a2 = fmaf(kv, Win[2 * D + d], a2);
        a3 = fmaf(kv, Win[3 * D + d], a3);
        cb = fmaf(kv, bin[d], cb);
    }
#pragma unroll
    for (int off = 16; off; off >>= 1) {
        a0 += __shfl_down_sync(0xffffffffu, a0, off);
        a1 += __shfl_down_sync(0xffffffffu, a1, off);
        a2 += __shfl_down_sync(0xffffffffu, a2, off);
        a3 += __shfl_down_sync(0xffffffffu, a3, off);
        cb += __shfl_down_sync(0xffffffffu, cb, off);
    }
    if (lane == 0) {
        g_P4[warp] = make_float4(a0 * S, a1 * S, a2 * S, a3 * S);
        g_c[warp]  = cb * S;
    }
}

// ---------------- K12: fused softmax row-norm + column-sum (exp evaluated ONCE) ----------------
// grid (G/QB, B), block NT. Block owns (b, 8 queries) over ALL k.
// Pass A: e = 2^(m.p + c) stored fp32 in smem E[k][8], Z accumulated per query.
// Pass B: w[k] += sum_q e * (1/Z_q); one atomicAdd per k per block.
extern __shared__ float k12_smem[];
__global__ void __launch_bounds__(NT, 1) k12(const float* __restrict__ mut) {
    float* sE   = k12_smem;             // G * 8 floats, row k at sE + k*8
    float* zbuf = k12_smem + G * QB;    // 16 warps * 8
    float* sr   = zbuf + (NT / 32) * QB;// 8 floats

    const int tid  = threadIdx.x;
    const int b    = blockIdx.y;
    const int q0   = blockIdx.x * QB;
    const int lane = tid & 31, warp = tid >> 5;

    // 8 query m-vectors
    float4 m[QB];
#pragma unroll
    for (int j = 0; j < QB; j++)
        m[j] = __ldg((const float4*)mut + (size_t)b * G + q0 + j);

    float z[QB];
#pragma unroll
    for (int j = 0; j < QB; j++) z[j] = 0.f;

    // ---- Pass A: scores -> exp -> smem, accumulate Z ----
    for (int k = tid; k < G; k += NT) {
        float4 p = __ldg(&g_P4[k]);
        float  c = __ldg(&g_c[k]);
        float e[QB];
#pragma unroll
        for (int j = 0; j < QB; j++) {
            float s = fmaf(m[j].x, p.x,
                      fmaf(m[j].y, p.y,
                      fmaf(m[j].z, p.z,
                      fmaf(m[j].w, p.w, c))));
            e[j] = ex2f(s);
            z[j] += e[j];
        }
        float4* row = (float4*)(sE + (size_t)k * QB);
        row[0] = make_float4(e[0], e[1], e[2], e[3]);
        row[1] = make_float4(e[4], e[5], e[6], e[7]);
    }

    // ---- Z reduction: within warp (disjoint k per lane), then across warps ----
#pragma unroll
    for (int j = 0; j < QB; j++) {
#pragma unroll
        for (int off = 16; off; off >>= 1)
            z[j] += __shfl_down_sync(0xffffffffu, z[j], off);
    }
    if (lane == 0) {
#pragma unroll
        for (int j = 0; j < QB; j++) zbuf[warp * QB + j] = z[j];
    }
    __syncthreads();
    if (tid < QB) {
        float Z = 0.f;
#pragma unroll
        for (int w = 0; w < NT / 32; w++) Z += zbuf[w * QB + tid];
        sr[tid] = 1.0f / Z;
    }
    __syncthreads();

    float r[QB];
#pragma unroll
    for (int j = 0; j < QB; j++) r[j] = sr[j];

    // ---- Pass B: column partial sums ----
    for (int k = tid; k < G; k += NT) {
        const float4* row = (const float4*)(sE + (size_t)k * QB);
        float4 a0 = row[0];
        float4 a1 = row[1];
        float wk = a0.x * r[0];
        wk = fmaf(a0.y, r[1], wk);
        wk = fmaf(a0.z, r[2], wk);
        wk = fmaf(a0.w, r[3], wk);
        wk = fmaf(a1.x, r[4], wk);
        wk = fmaf(a1.y, r[5], wk);
        wk = fmaf(a1.z, r[6], wk);
        wk = fmaf(a1.w, r[7], wk);
        atomicAdd(&g_acc[b * G + k], wk);
    }
}

// ---------------- K3a: mean partials = w @ V (all batches per block) ----------------
__global__ void k3a(const float* __restrict__ V) {
    int chunk = blockIdx.x;          // 0..136, 32 k each
    int d = threadIdx.x;             // 128
    int k0 = chunk * 32;
    float acc[B];
#pragma unroll
    for (int b = 0; b < B; b++) acc[b] = 0.f;
    for (int k = k0; k < k0 + 32; k++) {
        float v = V[(size_t)k * D + d];
#pragma unroll
        for (int b = 0; b < B; b++) acc[b] = fmaf(g_acc[b * G + k], v, acc[b]);
    }
#pragma unroll
    for (int b = 0; b < B; b++) atomicAdd(&g_acc[B * G + b * D + d], acc[b]);
}

// ---------------- K3b: GELU MLP head ----------------
__global__ void k3b(const float* __restrict__ W1, const float* __restrict__ b1,
                    const float* __restrict__ W2, const float* __restrict__ b2,
                    float* __restrict__ out) {
    __shared__ float mean[D];
    __shared__ float h[H1];
    int b = blockIdx.x, tid = threadIdx.x;
    mean[tid] = g_acc[B * G + b * D + tid] * (1.0f / (float)G);
    __syncthreads();
    if (tid < H1) {
        float a = b1[tid];
        for (int d = 0; d < D; d++) a = fmaf(mean[d], W1[d * H1 + tid], a);
        h[tid] = 0.5f * a * (1.0f + erff(a * 0.70710678118654752f));
    }
    __syncthreads();
    if (tid < NOUT) {
        float o = b2[tid];
        for (int j = 0; j < H1; j++) o = fmaf(h[j], W2[j * NOUT + tid], o);
        out[b * NOUT + tid] = o;
    }
}

// ---------------- launch ----------------
extern "C" void kernel_launch(void* const* d_in, const int* in_sizes, int n_in,
                              void* d_out, int out_size) {
    const float* mut = (const float*)d_in[0];   // [8,4384,4]
    const float* V   = (const float*)d_in[1];   // [4384,128]
    const float* Win = (const float*)d_in[2];   // [4,128]
    const float* bin = (const float*)d_in[3];   // [128]
    const float* Kp  = (const float*)d_in[4];   // [4384,128]
    const float* W1  = (const float*)d_in[5];   // [128,64]
    const float* b1  = (const float*)d_in[6];   // [64]
    const float* W2  = (const float*)d_in[7];   // [64,26]
    const float* b2  = (const float*)d_in[8];   // [26]
    float* out = (float*)d_out;                 // [8,26]
    (void)in_sizes; (void)n_in; (void)out_size;

    void* accPtr = nullptr;
    cudaGetSymbolAddress(&accPtr, g_acc);
    cudaMemsetAsync(accPtr, 0, sizeof(float) * (B * G + B * D), 0);

    k0_P<<<548, 256>>>(Win, bin, Kp);           // 548*8 warps = 4384 = G

    size_t smemK12 = (size_t)G * QB * 4 + (NT / 32) * QB * 4 + QB * 4;  // 140,832 B
    cudaFuncSetAttribute(k12, cudaFuncAttributeMaxDynamicSharedMemorySize, (int)smemK12);
    k12<<<dim3(G / QB, B), NT, smemK12>>>(mut);

    k3a<<<137, D>>>(V);
    k3b<<<B, D>>>(W1, b1, W2, b2, out);
}